// round 4
// baseline (speedup 1.0000x reference)
#include <cuda_runtime.h>
#include <math.h>

// RoI Align pyramid (FPN).
//   d_in[0] metadata [1,3] f32, d_in[1] boxes [1,1024,4] f32
//   d_in[2..5] p2..p5: [1,H,H,256] f32, H = 256,128,64,32
// Output: [1,1024,7,7,256] f32
//
// One block per box, 256 threads in 4 groups of 64 lanes; lane = one
// float4 channel chunk. Loop over samples unrolled x2 for MLP.
// Output stores use __stcs (evict-first) so the feature pyramid stays
// resident in L2 across graph replays.

#define EXTENT 7
#define NBOX   1024
#define CH4    64   // 256 channels / 4

__global__ __launch_bounds__(256, 8)
void roi_align_pyramid_kernel(const float* __restrict__ metadata,
                              const float* __restrict__ boxes,
                              const float* __restrict__ p2,
                              const float* __restrict__ p3,
                              const float* __restrict__ p4,
                              const float* __restrict__ p5,
                              float* __restrict__ out)
{
    const int box = blockIdx.x;

    const float rows = metadata[0];
    const float cols = metadata[1];

    const float x1 = boxes[box * 4 + 0];
    const float y1 = boxes[box * 4 + 1];
    const float x2 = boxes[box * 4 + 2];
    const float y2 = boxes[box * 4 + 3];

    const float h = y2 - y1;
    const float w = x2 - x1;

    // roi_level = clip(4 + round(log2(sqrt(h*w)/sqrt(rows*cols))), 2, 5)
    float rl = logf(sqrtf(h * w) / sqrtf(rows * cols)) * (1.0f / logf(2.0f));
    rl = fminf(5.0f, fmaxf(2.0f, 4.0f + rintf(rl)));
    const int lvl = (int)rl;  // 2..5

    const float* feat;
    int H;
    switch (lvl) {
        case 2: feat = p2; H = 256; break;
        case 3: feat = p3; H = 128; break;
        case 4: feat = p4; H = 64;  break;
        default: feat = p5; H = 32; break;
    }
    const int W = H;

    const float inv_r = 1.0f / (rows - 1.0f);
    const float inv_c = 1.0f / (cols - 1.0f);
    const float ny1 = y1 * inv_r;
    const float ny2 = y2 * inv_r;
    const float nx1 = x1 * inv_c;
    const float nx2 = x2 * inv_c;
    const float dny = ny2 - ny1;
    const float dnx = nx2 - nx1;
    const float Hm1 = (float)(H - 1);
    const float Wm1 = (float)(W - 1);

    const int t      = threadIdx.x;
    const int lane_c = t & (CH4 - 1);   // float4 channel index 0..63
    const int sgrp   = t >> 6;          // sample group 0..3

    const float4* __restrict__ f4 = (const float4*)feat;
    float4* __restrict__ o4 = (float4*)out + (size_t)box * (EXTENT * EXTENT * CH4);

    // Per-sample addressing: sample index s in [0,49)
    auto sample_setup = [&](int s, size_t& b00, size_t& rowstep,
                            float& w00, float& w01, float& w10, float& w11) {
        const int gy = s / EXTENT;
        const int gx = s - gy * EXTENT;

        const float gyf = (float)gy * (1.0f / (float)(EXTENT - 1));
        const float gxf = (float)gx * (1.0f / (float)(EXTENT - 1));

        const float ys = (ny1 + dny * gyf) * Hm1;
        const float xs = (nx1 + dnx * gxf) * Wm1;

        const float y0f = fminf(fmaxf(floorf(ys), 0.0f), (float)(H - 2));
        const float x0f = fminf(fmaxf(floorf(xs), 0.0f), (float)(W - 2));
        const float wy = ys - y0f;
        const float wx = xs - x0f;

        w00 = (1.0f - wy) * (1.0f - wx);
        w01 = (1.0f - wy) * wx;
        w10 = wy * (1.0f - wx);
        w11 = wy * wx;

        b00 = ((size_t)((int)y0f * W + (int)x0f)) * CH4 + lane_c;
        rowstep = (size_t)W * CH4;
    };

    int s = sgrp;
    // Unrolled x2: keep 8 gathers in flight
    for (; s + 4 < EXTENT * EXTENT; s += 8) {
        size_t a_b00, a_rs; float a00, a01, a10, a11;
        size_t b_b00, b_rs; float b00w, b01w, b10w, b11w;
        sample_setup(s,     a_b00, a_rs, a00, a01, a10, a11);
        sample_setup(s + 4, b_b00, b_rs, b00w, b01w, b10w, b11w);

        const float4 fa00 = __ldg(&f4[a_b00]);
        const float4 fa01 = __ldg(&f4[a_b00 + CH4]);
        const float4 fa10 = __ldg(&f4[a_b00 + a_rs]);
        const float4 fa11 = __ldg(&f4[a_b00 + a_rs + CH4]);
        const float4 fb00 = __ldg(&f4[b_b00]);
        const float4 fb01 = __ldg(&f4[b_b00 + CH4]);
        const float4 fb10 = __ldg(&f4[b_b00 + b_rs]);
        const float4 fb11 = __ldg(&f4[b_b00 + b_rs + CH4]);

        float4 ra;
        ra.x = fa00.x * a00 + fa01.x * a01 + fa10.x * a10 + fa11.x * a11;
        ra.y = fa00.y * a00 + fa01.y * a01 + fa10.y * a10 + fa11.y * a11;
        ra.z = fa00.z * a00 + fa01.z * a01 + fa10.z * a10 + fa11.z * a11;
        ra.w = fa00.w * a00 + fa01.w * a01 + fa10.w * a10 + fa11.w * a11;
        __stcs(&o4[s * CH4 + lane_c], ra);

        float4 rb;
        rb.x = fb00.x * b00w + fb01.x * b01w + fb10.x * b10w + fb11.x * b11w;
        rb.y = fb00.y * b00w + fb01.y * b01w + fb10.y * b10w + fb11.y * b11w;
        rb.z = fb00.z * b00w + fb01.z * b01w + fb10.z * b10w + fb11.z * b11w;
        rb.w = fb00.w * b00w + fb01.w * b01w + fb10.w * b10w + fb11.w * b11w;
        __stcs(&o4[(s + 4) * CH4 + lane_c], rb);
    }
    // Tail (at most one sample per group)
    if (s < EXTENT * EXTENT) {
        size_t b00i, rs; float w00, w01, w10, w11;
        sample_setup(s, b00i, rs, w00, w01, w10, w11);
        const float4 f00 = __ldg(&f4[b00i]);
        const float4 f01 = __ldg(&f4[b00i + CH4]);
        const float4 f10 = __ldg(&f4[b00i + rs]);
        const float4 f11 = __ldg(&f4[b00i + rs + CH4]);
        float4 r;
        r.x = f00.x * w00 + f01.x * w01 + f10.x * w10 + f11.x * w11;
        r.y = f00.y * w00 + f01.y * w01 + f10.y * w10 + f11.y * w11;
        r.z = f00.z * w00 + f01.z * w01 + f10.z * w10 + f11.z * w11;
        r.w = f00.w * w00 + f01.w * w01 + f10.w * w10 + f11.w * w11;
        __stcs(&o4[s * CH4 + lane_c], r);
    }
}

extern "C" void kernel_launch(void* const* d_in, const int* in_sizes, int n_in,
                              void* d_out, int out_size)
{
    const float* metadata = (const float*)d_in[0];
    const float* boxes    = (const float*)d_in[1];
    const float* p2       = (const float*)d_in[2];
    const float* p3       = (const float*)d_in[3];
    const float* p4       = (const float*)d_in[4];
    const float* p5       = (const float*)d_in[5];
    float* out = (float*)d_out;

    roi_align_pyramid_kernel<<<NBOX, 256>>>(metadata, boxes, p2, p3, p4, p5, out);
}

// round 5
// speedup vs baseline: 1.2269x; 1.2269x over previous
#include <cuda_runtime.h>
#include <math.h>

// RoI Align pyramid (FPN).
//   d_in[0] metadata [1,3] f32, d_in[1] boxes [1,1024,4] f32
//   d_in[2..5] p2..p5: [1,H,H,256] f32, H = 256,128,64,32
// Output: [1,1024,7,7,256] f32
//
// One block per box, 256 threads in 4 groups of 64 lanes; lane = one
// float4 channel chunk. Loop over samples unrolled x2 -> 8 independent
// LDG.128 in flight per thread. launch_bounds(256,4) allows ~64 regs so
// the unroll actually materializes (at 32 regs ptxas serializes it).
// 32-bit indexing throughout. Output stores streaming (__stcs).

#define EXTENT 7
#define NBOX   1024
#define CH4    64u   // 256 channels / 4

__global__ __launch_bounds__(256, 4)
void roi_align_pyramid_kernel(const float* __restrict__ metadata,
                              const float* __restrict__ boxes,
                              const float* __restrict__ p2,
                              const float* __restrict__ p3,
                              const float* __restrict__ p4,
                              const float* __restrict__ p5,
                              float* __restrict__ out)
{
    const int box = blockIdx.x;

    const float rows = metadata[0];
    const float cols = metadata[1];

    const float x1 = boxes[box * 4 + 0];
    const float y1 = boxes[box * 4 + 1];
    const float x2 = boxes[box * 4 + 2];
    const float y2 = boxes[box * 4 + 3];

    const float h = y2 - y1;
    const float w = x2 - x1;

    // roi_level = clip(4 + round(log2(sqrt(h*w)/sqrt(rows*cols))), 2, 5)
    float rl = logf(sqrtf(h * w) / sqrtf(rows * cols)) * (1.0f / logf(2.0f));
    rl = fminf(5.0f, fmaxf(2.0f, 4.0f + rintf(rl)));
    const int lvl = (int)rl;  // 2..5

    const float* feat;
    int H;
    switch (lvl) {
        case 2: feat = p2; H = 256; break;
        case 3: feat = p3; H = 128; break;
        case 4: feat = p4; H = 64;  break;
        default: feat = p5; H = 32; break;
    }
    const int W = H;

    const float inv_r = 1.0f / (rows - 1.0f);
    const float inv_c = 1.0f / (cols - 1.0f);
    const float ny1 = y1 * inv_r;
    const float ny2 = y2 * inv_r;
    const float nx1 = x1 * inv_c;
    const float nx2 = x2 * inv_c;
    const float dny = ny2 - ny1;
    const float dnx = nx2 - nx1;
    const float Hm1 = (float)(H - 1);
    const float Wm1 = (float)(W - 1);

    const unsigned t      = threadIdx.x;
    const unsigned lane_c = t & (CH4 - 1u);  // float4 channel index 0..63
    const unsigned sgrp   = t >> 6;          // sample group 0..3
    const unsigned rowstep = (unsigned)W * CH4;

    const float4* __restrict__ f4 = (const float4*)feat;
    float4* __restrict__ o4 = (float4*)out + (unsigned)box * (EXTENT * EXTENT * CH4);

    // Per-sample addressing: sample index s in [0,49)
    auto sample_setup = [&](int s, unsigned& b00,
                            float& w00, float& w01, float& w10, float& w11) {
        const int gy = s / EXTENT;
        const int gx = s - gy * EXTENT;

        const float gyf = (float)gy * (1.0f / (float)(EXTENT - 1));
        const float gxf = (float)gx * (1.0f / (float)(EXTENT - 1));

        const float ys = (ny1 + dny * gyf) * Hm1;
        const float xs = (nx1 + dnx * gxf) * Wm1;

        const float y0f = fminf(fmaxf(floorf(ys), 0.0f), (float)(H - 2));
        const float x0f = fminf(fmaxf(floorf(xs), 0.0f), (float)(W - 2));
        const float wy = ys - y0f;
        const float wx = xs - x0f;

        w00 = (1.0f - wy) * (1.0f - wx);
        w01 = (1.0f - wy) * wx;
        w10 = wy * (1.0f - wx);
        w11 = wy * wx;

        b00 = ((unsigned)((int)y0f * W + (int)x0f)) * CH4 + lane_c;
    };

    int s = (int)sgrp;
    // Unrolled x2: 8 independent LDG.128 in flight per thread
    for (; s + 4 < EXTENT * EXTENT; s += 8) {
        unsigned a_b00; float a00, a01, a10, a11;
        unsigned b_b00; float b00w, b01w, b10w, b11w;
        sample_setup(s,     a_b00, a00, a01, a10, a11);
        sample_setup(s + 4, b_b00, b00w, b01w, b10w, b11w);

        const float4 fa00 = __ldg(&f4[a_b00]);
        const float4 fa01 = __ldg(&f4[a_b00 + CH4]);
        const float4 fa10 = __ldg(&f4[a_b00 + rowstep]);
        const float4 fa11 = __ldg(&f4[a_b00 + rowstep + CH4]);
        const float4 fb00 = __ldg(&f4[b_b00]);
        const float4 fb01 = __ldg(&f4[b_b00 + CH4]);
        const float4 fb10 = __ldg(&f4[b_b00 + rowstep]);
        const float4 fb11 = __ldg(&f4[b_b00 + rowstep + CH4]);

        float4 ra;
        ra.x = fa00.x * a00 + fa01.x * a01 + fa10.x * a10 + fa11.x * a11;
        ra.y = fa00.y * a00 + fa01.y * a01 + fa10.y * a10 + fa11.y * a11;
        ra.z = fa00.z * a00 + fa01.z * a01 + fa10.z * a10 + fa11.z * a11;
        ra.w = fa00.w * a00 + fa01.w * a01 + fa10.w * a10 + fa11.w * a11;
        __stcs(&o4[(unsigned)s * CH4 + lane_c], ra);

        float4 rb;
        rb.x = fb00.x * b00w + fb01.x * b01w + fb10.x * b10w + fb11.x * b11w;
        rb.y = fb00.y * b00w + fb01.y * b01w + fb10.y * b10w + fb11.y * b11w;
        rb.z = fb00.z * b00w + fb01.z * b01w + fb10.z * b10w + fb11.z * b11w;
        rb.w = fb00.w * b00w + fb01.w * b01w + fb10.w * b10w + fb11.w * b11w;
        __stcs(&o4[(unsigned)(s + 4) * CH4 + lane_c], rb);
    }
    // Tail (at most one sample per group)
    if (s < EXTENT * EXTENT) {
        unsigned b00i; float w00, w01, w10, w11;
        sample_setup(s, b00i, w00, w01, w10, w11);
        const float4 f00 = __ldg(&f4[b00i]);
        const float4 f01 = __ldg(&f4[b00i + CH4]);
        const float4 f10 = __ldg(&f4[b00i + rowstep]);
        const float4 f11 = __ldg(&f4[b00i + rowstep + CH4]);
        float4 r;
        r.x = f00.x * w00 + f01.x * w01 + f10.x * w10 + f11.x * w11;
        r.y = f00.y * w00 + f01.y * w01 + f10.y * w10 + f11.y * w11;
        r.z = f00.z * w00 + f01.z * w01 + f10.z * w10 + f11.z * w11;
        r.w = f00.w * w00 + f01.w * w01 + f10.w * w10 + f11.w * w11;
        __stcs(&o4[(unsigned)s * CH4 + lane_c], r);
    }
}

extern "C" void kernel_launch(void* const* d_in, const int* in_sizes, int n_in,
                              void* d_out, int out_size)
{
    const float* metadata = (const float*)d_in[0];
    const float* boxes    = (const float*)d_in[1];
    const float* p2       = (const float*)d_in[2];
    const float* p3       = (const float*)d_in[3];
    const float* p4       = (const float*)d_in[4];
    const float* p5       = (const float*)d_in[5];
    float* out = (float*)d_out;

    roi_align_pyramid_kernel<<<NBOX, 256>>>(metadata, boxes, p2, p3, p4, p5, out);
}